// round 1
// baseline (speedup 1.0000x reference)
#include <cuda_runtime.h>
#include <math.h>
#include <stdint.h>

#define T_LEN 64
#define BATCH 32
#define SEQ   400
#define HID   512
#define VOC   50000
#define EXTD  400
#define VE    (VOC+EXTD)
#define TB    (T_LEN*BATCH)     /* 2048 */
#define H3    (3*HID)           /* 1536 */

/* ---------------- scratch (device globals: allocation-free) -------------- */
__device__ float g_cat [TB*H3];             /* (T*B, 3H) rows t*B+b          */
__device__ float g_qB  [BATCH*T_LEN*HID];   /* (B,T,H)                       */
__device__ float g_kB  [BATCH*SEQ*HID];     /* (B,S,H)                       */
__device__ float g_valT[BATCH*HID*SEQ];     /* (B,H,S)                       */
__device__ float g_w   [BATCH*T_LEN*SEQ];   /* (B,T,S) attn weights          */
__device__ float g_atts[TB*HID];            /* (B,T,H) rows b*T+t            */
__device__ float g_gate[TB];

/* ---------------- generic TF32 MMA GEMM: C = alpha*(A@B^T + bias) -------- */
struct GP {
  const float* A; const float* B; float* C;
  long lda, ldb, ldc;
  long sA, sB, sC;            /* batch strides (grid.z)                      */
  int  M, N, K;
  const float* bias;          /* per-n bias or nullptr                       */
  float alpha;
  int  mode, D1, D2, D3;      /* epilogue index modes (see epi())            */
  long col_off;
};

#define BM 128
#define BN 128
#define BK 32
#define LDSM 36                 /* BK + 4 pad: conflict-free, 16B aligned    */
#define STAGE (BM*LDSM)         /* floats per stage per operand              */

__device__ __forceinline__ void cpa16(float* dst, const float* src, int bytes){
  unsigned d = (unsigned)__cvta_generic_to_shared(dst);
  asm volatile("cp.async.ca.shared.global [%0], [%1], 16, %2;\n"
               :: "r"(d), "l"(src), "r"(bytes));
}
__device__ __forceinline__ unsigned to_tf32(float x){
  unsigned r; asm("cvt.rna.tf32.f32 %0, %1;" : "=r"(r) : "f"(x)); return r;
}

__device__ __forceinline__ void epi(const GP& p, float* C, int m, int n, float v){
  if (m >= p.M || n >= p.N) return;
  float b = p.bias ? p.bias[n] : 0.f;
  float o = p.alpha * (v + b);
  long idx;
  if (p.mode == 0)      idx = (long)m * p.ldc + p.col_off + n;
  else if (p.mode == 1) idx = (long)((m % p.D1) * p.D2 + m / p.D1) * p.ldc + p.col_off + n;
  else                  idx = ((long)(m % p.D1) * p.D2 + n) * (long)p.D3 + (m / p.D1);
  C[idx] = o;
}

__global__ __launch_bounds__(256) void gemm_tf32(GP p){
  extern __shared__ float smf[];
  float* As = smf;
  float* Bs = smf + 2*STAGE;
  const float* A  = p.A + (long)blockIdx.z * p.sA;
  const float* Bg = p.B + (long)blockIdx.z * p.sB;
  float*       C  = p.C + (long)blockIdx.z * p.sC;

  int tid = threadIdx.x;
  int lane = tid & 31, warp = tid >> 5;
  int wm = warp & 3, wn = warp >> 1 >> 1;        /* wn = warp >> 2 */
  wn = warp >> 2;
  int m0 = blockIdx.x * BM, n0 = blockIdx.y * BN;

  float acc[2][8][4];
  #pragma unroll
  for (int i=0;i<2;i++)
    #pragma unroll
    for (int j=0;j<8;j++){ acc[i][j][0]=0.f; acc[i][j][1]=0.f; acc[i][j][2]=0.f; acc[i][j][3]=0.f; }

  int ktiles = (p.K + BK - 1)/BK;
  int rowl = tid >> 3;            /* 0..31  */
  int col4 = (tid & 7) * 4;       /* 0..28  */

  auto load = [&](int st, int k0){
    #pragma unroll
    for (int i=0;i<4;i++){
      int r  = rowl + i*32;
      int kleft = p.K - (k0 + col4);
      int kb = (kleft >= 4) ? 16 : (kleft > 0 ? kleft*4 : 0);
      int gm = m0 + r;
      cpa16(As + st*STAGE + r*LDSM + col4, A + (long)gm*p.lda + k0 + col4,
            (gm < p.M) ? kb : 0);
      int gn = n0 + r;
      cpa16(Bs + st*STAGE + r*LDSM + col4, Bg + (long)gn*p.ldb + k0 + col4,
            (gn < p.N) ? kb : 0);
    }
  };

  load(0, 0);
  asm volatile("cp.async.commit_group;\n");

  for (int kt=0; kt<ktiles; kt++){
    if (kt+1 < ktiles) load((kt+1)&1, (kt+1)*BK);
    asm volatile("cp.async.commit_group;\n");
    asm volatile("cp.async.wait_group 1;\n");
    __syncthreads();

    const float* Ab = As + (kt&1)*STAGE;
    const float* Bb = Bs + (kt&1)*STAGE;
    int r = lane >> 2, c = lane & 3;
    #pragma unroll
    for (int kk=0; kk<4; kk++){
      int kb = kk*8;
      unsigned af[2][4], bf[8][2];
      #pragma unroll
      for (int im=0; im<2; im++){
        int mr = wm*32 + im*16 + r;
        af[im][0] = to_tf32(Ab[ mr   *LDSM + kb + c    ]);
        af[im][1] = to_tf32(Ab[(mr+8)*LDSM + kb + c    ]);
        af[im][2] = to_tf32(Ab[ mr   *LDSM + kb + c + 4]);
        af[im][3] = to_tf32(Ab[(mr+8)*LDSM + kb + c + 4]);
      }
      #pragma unroll
      for (int jn=0; jn<8; jn++){
        int nc = wn*64 + jn*8 + r;
        bf[jn][0] = to_tf32(Bb[nc*LDSM + kb + c    ]);
        bf[jn][1] = to_tf32(Bb[nc*LDSM + kb + c + 4]);
      }
      #pragma unroll
      for (int im=0; im<2; im++)
        #pragma unroll
        for (int jn=0; jn<8; jn++){
          float* d = acc[im][jn];
          asm volatile(
            "mma.sync.aligned.m16n8k8.row.col.f32.tf32.tf32.f32 "
            "{%0,%1,%2,%3}, {%4,%5,%6,%7}, {%8,%9}, {%0,%1,%2,%3};\n"
            : "+f"(d[0]), "+f"(d[1]), "+f"(d[2]), "+f"(d[3])
            : "r"(af[im][0]), "r"(af[im][1]), "r"(af[im][2]), "r"(af[im][3]),
              "r"(bf[jn][0]), "r"(bf[jn][1]));
        }
    }
    __syncthreads();
  }

  int r = lane >> 2, c2 = (lane & 3)*2;
  #pragma unroll
  for (int im=0; im<2; im++)
    #pragma unroll
    for (int jn=0; jn<8; jn++){
      int mr = m0 + wm*32 + im*16 + r;
      int nc = n0 + wn*64 + jn*8 + c2;
      epi(p, C, mr,   nc,   acc[im][jn][0]);
      epi(p, C, mr,   nc+1, acc[im][jn][1]);
      epi(p, C, mr+8, nc,   acc[im][jn][2]);
      epi(p, C, mr+8, nc+1, acc[im][jn][3]);
    }
}

/* ---------------- cat[:, 0:1024] = [h, y_emb] ---------------------------- */
__global__ void cat_copy(const float* __restrict__ h, const float* __restrict__ y){
  int i = blockIdx.x*blockDim.x + threadIdx.x;
  if (i >= TB*(HID/4)) return;
  int row = i / (HID/4);
  int c   = i % (HID/4);
  const float4* h4 = (const float4*)h;
  const float4* y4 = (const float4*)y;
  float4* cat4 = (float4*)g_cat;
  cat4[(long)row*(H3/4) + c]           = h4[i];
  cat4[(long)row*(H3/4) + (HID/4) + c] = y4[i];
}

/* ---------------- softmax over S; writes w (B,T,S) + dists (T,B,S) ------- */
__global__ void softmax_s(float* __restrict__ dists, const unsigned char* __restrict__ mask){
  int bt = blockIdx.x;                  /* b*T + t */
  int b = bt / T_LEN, t = bt % T_LEN;
  float* row = g_w + (long)bt*SEQ;
  const unsigned char* mrow = mask + (long)b*SEQ;
  int tid = threadIdx.x;                /* 128 */
  __shared__ float red[128];
  float mx = -1e30f;
  for (int s=tid; s<SEQ; s+=128){
    float x = mrow[s] ? -1e9f : row[s];
    mx = fmaxf(mx, x);
  }
  red[tid]=mx; __syncthreads();
  for (int off=64; off>0; off>>=1){ if (tid<off) red[tid]=fmaxf(red[tid],red[tid+off]); __syncthreads(); }
  mx = red[0]; __syncthreads();
  float sum=0.f;
  for (int s=tid; s<SEQ; s+=128){
    float x = mrow[s] ? -1e9f : row[s];
    sum += __expf(x-mx);
  }
  red[tid]=sum; __syncthreads();
  for (int off=64; off>0; off>>=1){ if (tid<off) red[tid]+=red[tid+off]; __syncthreads(); }
  float inv = 1.f/red[0];
  for (int s=tid; s<SEQ; s+=128){
    float x = mrow[s] ? -1e9f : row[s];
    float wv = __expf(x-mx)*inv;
    row[s] = wv;
    dists[((long)t*BATCH + b)*SEQ + s] = wv;
  }
}

/* ---------------- gate g = sigmoid(cat . v + bv) ------------------------- */
__global__ void gate_k(const float* __restrict__ v, const float* __restrict__ bv){
  int row = blockIdx.x;
  int tid = threadIdx.x;                /* 256 */
  __shared__ float red[256];
  const float* cr = g_cat + (long)row*H3;
  float s=0.f;
  for (int j=tid; j<H3; j+=256) s += cr[j]*v[j];
  red[tid]=s; __syncthreads();
  for (int off=128; off>0; off>>=1){ if (tid<off) red[tid]+=red[tid+off]; __syncthreads(); }
  if (tid==0) g_gate[row] = 1.f/(1.f+__expf(-(red[0]+bv[0])));
}

/* ------- softmax over V (in d_out) fused with gate scale + ext zero ------ */
__global__ void softmax_v(float* __restrict__ out){
  int rid = blockIdx.x;                 /* t*B + b */
  float* row = out + (long)rid*VE;
  int tid = threadIdx.x;                /* 512 */
  __shared__ float rm[512], rs[512];
  float m = row[tid], s = 1.f;          /* every tid<512 has >=1 elem        */
  for (int j=tid+512; j<VOC; j+=512){
    float x = row[j];
    if (x > m){ s = s*__expf(m-x) + 1.f; m = x; }
    else        s += __expf(x-m);
  }
  rm[tid]=m; rs[tid]=s; __syncthreads();
  for (int off=256; off>0; off>>=1){
    if (tid<off){
      float m2=rm[tid+off], s2=rs[tid+off];
      float M=fmaxf(rm[tid],m2);
      rs[tid]=rs[tid]*__expf(rm[tid]-M)+s2*__expf(m2-M);
      rm[tid]=M;
    }
    __syncthreads();
  }
  float M = rm[0];
  float gscale = g_gate[rid]/rs[0];
  for (int j=tid; j<VOC; j+=512) row[j] = __expf(row[j]-M)*gscale;
  for (int j=VOC+tid; j<VE; j+=512) row[j] = 0.f;
}

/* ---------------- scatter: pred[t,b,xids[s,b]] += (1-g)*dists ------------ */
__global__ void scatter_k(float* __restrict__ out, const int* __restrict__ xids){
  long i = (long)blockIdx.x*blockDim.x + threadIdx.x;
  if (i >= (long)TB*SEQ) return;
  int tb = (int)(i / SEQ);              /* t*B + b */
  int s  = (int)(i % SEQ);
  int b = tb % BATCH, t = tb / BATCH;
  float wv = g_w[((long)b*T_LEN + t)*SEQ + s];
  float gg = g_gate[tb];
  int col = xids[(long)s*BATCH + b];
  atomicAdd(out + (long)tb*VE + col, (1.f-gg)*wv);
}

/* ------------------------------- host ----------------------------------- */
static inline void launch_gemm(const GP& p, int batches, int smem){
  dim3 grid((p.M+BM-1)/BM, (p.N+BN-1)/BN, batches);
  gemm_tf32<<<grid, 256, smem>>>(p);
}

extern "C" void kernel_launch(void* const* d_in, const int* in_sizes, int n_in,
                              void* d_out, int out_size){
  const float* h    = (const float*)d_in[0];
  const float* yemb = (const float*)d_in[1];
  const float* mem  = (const float*)d_in[2];
  const unsigned char* mask = (const unsigned char*)d_in[3];
  const int* xids   = (const int*)d_in[4];
  int wb = 5;
  if (n_in >= 18 && in_sizes[5] == 1) wb = 6;   /* max_ext_len scalar present */
  const float* Wq = (const float*)d_in[wb+0];
  const float* bq = (const float*)d_in[wb+1];
  const float* Wk = (const float*)d_in[wb+2];
  const float* bk = (const float*)d_in[wb+3];
  const float* Wv = (const float*)d_in[wb+4];
  const float* bva= (const float*)d_in[wb+5];
  const float* Wo = (const float*)d_in[wb+6];
  const float* bo = (const float*)d_in[wb+7];
  const float* Wp = (const float*)d_in[wb+8];
  const float* bp = (const float*)d_in[wb+9];
  const float* vv = (const float*)d_in[wb+10];
  const float* bv = (const float*)d_in[wb+11];

  float* out   = (float*)d_out;
  float* dists = out + (long)TB*VE;

  int smem = 4*STAGE*(int)sizeof(float);    /* 73728 B */
  cudaFuncSetAttribute(gemm_tf32, cudaFuncAttributeMaxDynamicSharedMemorySize, smem);

  void *qB, *kB, *valT, *wbuf, *attsB, *catp;
  cudaGetSymbolAddress(&qB,   g_qB);
  cudaGetSymbolAddress(&kB,   g_kB);
  cudaGetSymbolAddress(&valT, g_valT);
  cudaGetSymbolAddress(&wbuf, g_w);
  cudaGetSymbolAddress(&attsB,g_atts);
  cudaGetSymbolAddress(&catp, g_cat);

  float scale = 1.0f/sqrtf((float)HID);

  /* cat[:,0:1024] = [h, y_emb] */
  cat_copy<<<(TB*(HID/4)+255)/256, 256>>>(h, yemb);

  GP p;
  /* q = (h@Wq^T + bq)*scale  ->  (B,T,H) */
  p = GP{h, Wq, (float*)qB, HID, HID, HID, 0,0,0, TB, HID, HID,
         bq, scale, 1, BATCH, T_LEN, 0, 0};
  launch_gemm(p, 1, smem);
  /* k = memory@Wk^T + bk  ->  (B,S,H) */
  p = GP{mem, Wk, (float*)kB, HID, HID, HID, 0,0,0, SEQ*BATCH, HID, HID,
         bk, 1.f, 1, BATCH, SEQ, 0, 0};
  launch_gemm(p, 1, smem);
  /* val = memory@Wv^T + bv_attn  ->  (B,H,S) transposed */
  p = GP{mem, Wv, (float*)valT, HID, HID, 0, 0,0,0, SEQ*BATCH, HID, HID,
         bva, 1.f, 2, BATCH, HID, SEQ, 0};
  launch_gemm(p, 1, smem);
  /* scores[b]: (T,S) = q_b @ k_b^T   (batched over B) */
  p = GP{(const float*)qB, (const float*)kB, (float*)wbuf, HID, HID, SEQ,
         (long)T_LEN*HID, (long)SEQ*HID, (long)T_LEN*SEQ,
         T_LEN, SEQ, HID, nullptr, 1.f, 0, 0,0,0, 0};
  launch_gemm(p, BATCH, smem);
  /* softmax over S, write w + dists */
  softmax_s<<<BATCH*T_LEN, 128>>>(dists, mask);
  /* atts[b]: (T,H) = w_b @ valT_b^T   (batched over B) */
  p = GP{(const float*)wbuf, (const float*)valT, (float*)attsB, SEQ, SEQ, HID,
         (long)T_LEN*SEQ, (long)HID*SEQ, (long)T_LEN*HID,
         T_LEN, HID, SEQ, nullptr, 1.f, 0, 0,0,0, 0};
  launch_gemm(p, BATCH, smem);
  /* cat[:,1024:1536] = atts@Wo^T + bo  (rows b*T+t -> t*B+b) */
  p = GP{(const float*)attsB, Wo, (float*)catp, HID, HID, H3, 0,0,0,
         TB, HID, HID, bo, 1.f, 1, T_LEN, BATCH, 0, 1024};
  launch_gemm(p, 1, smem);
  /* gate */
  gate_k<<<TB, 256>>>(vv, bv);
  /* logits = cat@Wp^T + bp  -> d_out rows, ldc = V+EXT */
  p = GP{(const float*)catp, Wp, out, H3, H3, VE, 0,0,0,
         TB, VOC, H3, bp, 1.f, 0, 0,0,0, 0};
  launch_gemm(p, 1, smem);
  /* softmax over V fused with gate + ext zeroing */
  softmax_v<<<TB, 512>>>(out);
  /* pointer-mechanism scatter */
  scatter_k<<<(TB*SEQ + 255)/256, 256>>>(out, xids);

  (void)out_size; (void)n_in;
}

// round 3
// speedup vs baseline: 1.1091x; 1.1091x over previous
#include <cuda_runtime.h>
#include <math.h>
#include <stdint.h>

#define T_LEN 64
#define BATCH 32
#define SEQ   400
#define HID   512
#define VOC   50000
#define EXTD  400
#define VE    (VOC+EXTD)
#define TB    (T_LEN*BATCH)     /* 2048 */
#define H3    (3*HID)           /* 1536 */

/* ---------------- scratch (device globals: allocation-free) -------------- */
__device__ float g_cat [TB*H3];             /* (T*B, 3H) rows t*B+b          */
__device__ float g_qB  [BATCH*T_LEN*HID];   /* (B,T,H)                       */
__device__ float g_kB  [BATCH*SEQ*HID];     /* (B,S,H)                       */
__device__ float g_valT[BATCH*HID*SEQ];     /* (B,H,S)                       */
__device__ float g_w   [BATCH*T_LEN*SEQ];   /* (B,T,S) attn weights          */
__device__ float g_atts[TB*HID];            /* (B,T,H) rows b*T+t            */
__device__ float g_gate[TB];

/* ---------------- generic TF32 MMA GEMM: C = alpha*(A@B^T + bias) -------- */
struct GP {
  const float* A; const float* B; float* C;
  long lda, ldb, ldc;
  long sA, sB, sC;            /* batch strides (grid.z)                      */
  int  M, N, K;
  const float* bias;
  float alpha;
  int  mode, D1, D2, D3;      /* epilogue index modes                        */
  long col_off;
};

#define BM 128
#define BN 128
#define BK 32
#define ABYTES (BM*BK*4)        /* 16384 */
#define SBY    (2*ABYTES)       /* 32768 per stage (A then B)                */
#define NSTG   3
#define GSMEM  (NSTG*SBY)       /* 98304                                      */

__device__ __forceinline__ void cpa16u(unsigned dst, const float* src, int bytes){
  asm volatile("cp.async.cg.shared.global [%0], [%1], 16, %2;\n"
               :: "r"(dst), "l"(src), "r"(bytes));
}
#define CPA_COMMIT() asm volatile("cp.async.commit_group;\n")
#define CPA_WAIT2()  asm volatile("cp.async.wait_group 2;\n")

#define LDSM_X4(r0,r1,r2,r3,addr) \
  asm volatile("ldmatrix.sync.aligned.m8n8.x4.shared.b16 {%0,%1,%2,%3}, [%4];" \
               : "=r"(r0), "=r"(r1), "=r"(r2), "=r"(r3) : "r"(addr))

#define MMA8(d, a0,a1,a2,a3, b0,b1) \
  asm volatile("mma.sync.aligned.m16n8k8.row.col.f32.tf32.tf32.f32 " \
               "{%0,%1,%2,%3}, {%4,%5,%6,%7}, {%8,%9}, {%0,%1,%2,%3};\n" \
               : "+f"((d)[0]), "+f"((d)[1]), "+f"((d)[2]), "+f"((d)[3]) \
               : "r"(a0), "r"(a1), "r"(a2), "r"(a3), "r"(b0), "r"(b1))

__device__ __forceinline__ void epi(const GP& p, float* C, int m, int n, float v){
  if (m >= p.M || n >= p.N) return;
  float b = p.bias ? p.bias[n] : 0.f;
  float o = p.alpha * (v + b);
  long idx;
  if (p.mode == 0)      idx = (long)m * p.ldc + p.col_off + n;
  else if (p.mode == 1) idx = (long)((m % p.D1) * p.D2 + m / p.D1) * p.ldc + p.col_off + n;
  else                  idx = ((long)(m % p.D1) * p.D2 + n) * (long)p.D3 + (m / p.D1);
  C[idx] = o;
}

__global__ __launch_bounds__(256) void gemm_tf32(GP p){
  extern __shared__ float smf[];
  uint32_t sbase = (uint32_t)__cvta_generic_to_shared(smf);
  const float* A  = p.A + (long)blockIdx.z * p.sA;
  const float* Bg = p.B + (long)blockIdx.z * p.sB;
  float*       C  = p.C + (long)blockIdx.z * p.sC;

  int tid = threadIdx.x;
  int lane = tid & 31, warp = tid >> 5;
  int wm = warp & 3, wn = warp >> 2;
  int m0 = blockIdx.x * BM, n0 = blockIdx.y * BN;

  float acc[2][8][4];
  #pragma unroll
  for (int i=0;i<2;i++)
    #pragma unroll
    for (int j=0;j<8;j++){ acc[i][j][0]=0.f; acc[i][j][1]=0.f; acc[i][j][2]=0.f; acc[i][j][3]=0.f; }

  int ktiles = (p.K + BK - 1)/BK;

  /* cp.async staging: 16B granules, swizzle g ^= (row & 7)                  */
  auto load = [&](int st, int k0){
    uint32_t ab = sbase + st*SBY;
    uint32_t bb = ab + ABYTES;
    #pragma unroll
    for (int i=0;i<4;i++){
      int g = tid + i*256;              /* 0..1023 */
      int r = g >> 3, gc = g & 7;
      int kcol = k0 + gc*4;
      int kleft = p.K - kcol;
      int kb = (kleft >= 4) ? 16 : (kleft > 0 ? kleft*4 : 0);
      uint32_t soff = (uint32_t)(r*128 + ((gc ^ (r&7))<<4));
      int gm = m0 + r;
      cpa16u(ab + soff, A + (long)gm*p.lda + kcol, (gm < p.M) ? kb : 0);
      int gn = n0 + r;
      cpa16u(bb + soff, Bg + (long)gn*p.ldb + kcol, (gn < p.N) ? kb : 0);
    }
  };

  load(0, 0); CPA_COMMIT();
  load(1, BK); CPA_COMMIT();

  /* per-lane LDSM source rows */
  int mi1 = (lane >> 3) & 1;            /* matrix pair select (rows +8)      */
  int kg2 = lane >> 4;                  /* k-granule select (+1)             */
  int ri  = lane & 7;
  int marow = wm*32 + mi1*8 + ri;       /* A row for im=0                    */
  int nbrow = wn*64 + mi1*8 + ri;       /* B row for jp=0                    */
  int maxor = (marow & 7);
  int nbxor = (nbrow & 7);

  for (int kt = 0; kt < ktiles; kt++){
    if (kt + 2 < ktiles) load((kt+2)%NSTG, (kt+2)*BK);
    CPA_COMMIT();
    CPA_WAIT2();
    __syncthreads();

    uint32_t ab = sbase + (kt%NSTG)*SBY;
    uint32_t bb = ab + ABYTES;
    uint32_t aA = ab + marow*128;
    uint32_t aB = bb + nbrow*128;

    #pragma unroll
    for (int kk=0; kk<4; kk++){
      uint32_t asw = (uint32_t)(((kk*2 + kg2) ^ maxor) << 4);
      uint32_t bsw = (uint32_t)(((kk*2 + kg2) ^ nbxor) << 4);
      unsigned af0[4], af1[4], bf[4][4];
      LDSM_X4(af0[0],af0[1],af0[2],af0[3], aA + asw);
      LDSM_X4(af1[0],af1[1],af1[2],af1[3], aA + asw + 16*128);
      #pragma unroll
      for (int jp=0; jp<4; jp++)
        LDSM_X4(bf[jp][0],bf[jp][1],bf[jp][2],bf[jp][3], aB + bsw + jp*16*128);
      #pragma unroll
      for (int jp=0; jp<4; jp++){
        MMA8(acc[0][2*jp  ], af0[0],af0[1],af0[2],af0[3], bf[jp][0], bf[jp][2]);
        MMA8(acc[0][2*jp+1], af0[0],af0[1],af0[2],af0[3], bf[jp][1], bf[jp][3]);
        MMA8(acc[1][2*jp  ], af1[0],af1[1],af1[2],af1[3], bf[jp][0], bf[jp][2]);
        MMA8(acc[1][2*jp+1], af1[0],af1[1],af1[2],af1[3], bf[jp][1], bf[jp][3]);
      }
    }
    __syncthreads();
  }

  int r = lane >> 2, c2 = (lane & 3)*2;
  #pragma unroll
  for (int im=0; im<2; im++)
    #pragma unroll
    for (int jn=0; jn<8; jn++){
      int mr = m0 + wm*32 + im*16 + r;
      int nc = n0 + wn*64 + jn*8 + c2;
      epi(p, C, mr,   nc,   acc[im][jn][0]);
      epi(p, C, mr,   nc+1, acc[im][jn][1]);
      epi(p, C, mr+8, nc,   acc[im][jn][2]);
      epi(p, C, mr+8, nc+1, acc[im][jn][3]);
    }
}

/* ---------------- cat[:, 0:1024] = [h, y_emb] ---------------------------- */
__global__ void cat_copy(const float* __restrict__ h, const float* __restrict__ y){
  int i = blockIdx.x*blockDim.x + threadIdx.x;
  if (i >= TB*(HID/4)) return;
  int row = i / (HID/4);
  int c   = i % (HID/4);
  const float4* h4 = (const float4*)h;
  const float4* y4 = (const float4*)y;
  float4* cat4 = (float4*)g_cat;
  cat4[(long)row*(H3/4) + c]           = h4[i];
  cat4[(long)row*(H3/4) + (HID/4) + c] = y4[i];
}

/* ---------------- softmax over S; writes w (B,T,S) + dists (T,B,S) ------- */
__global__ void softmax_s(float* __restrict__ dists, const unsigned char* __restrict__ mask){
  int bt = blockIdx.x;                  /* b*T + t */
  int b = bt / T_LEN, t = bt % T_LEN;
  float* row = g_w + (long)bt*SEQ;
  const unsigned char* mrow = mask + (long)b*SEQ;
  int tid = threadIdx.x;                /* 128 */
  __shared__ float red[128];
  float mx = -1e30f;
  for (int s=tid; s<SEQ; s+=128){
    float x = mrow[s] ? -1e9f : row[s];
    mx = fmaxf(mx, x);
  }
  red[tid]=mx; __syncthreads();
  for (int off=64; off>0; off>>=1){ if (tid<off) red[tid]=fmaxf(red[tid],red[tid+off]); __syncthreads(); }
  mx = red[0]; __syncthreads();
  float sum=0.f;
  for (int s=tid; s<SEQ; s+=128){
    float x = mrow[s] ? -1e9f : row[s];
    sum += __expf(x-mx);
  }
  red[tid]=sum; __syncthreads();
  for (int off=64; off>0; off>>=1){ if (tid<off) red[tid]+=red[tid+off]; __syncthreads(); }
  float inv = 1.f/red[0];
  for (int s=tid; s<SEQ; s+=128){
    float x = mrow[s] ? -1e9f : row[s];
    float wv = __expf(x-mx)*inv;
    row[s] = wv;
    dists[((long)t*BATCH + b)*SEQ + s] = wv;
  }
}

/* ---------------- gate g = sigmoid(cat . v + bv) ------------------------- */
__global__ void gate_k(const float* __restrict__ v, const float* __restrict__ bv){
  int row = blockIdx.x;
  int tid = threadIdx.x;                /* 256 */
  __shared__ float red[256];
  const float* cr = g_cat + (long)row*H3;
  float s=0.f;
  for (int j=tid; j<H3; j+=256) s += cr[j]*v[j];
  red[tid]=s; __syncthreads();
  for (int off=128; off>0; off>>=1){ if (tid<off) red[tid]+=red[tid+off]; __syncthreads(); }
  if (tid==0) g_gate[row] = 1.f/(1.f+__expf(-(red[0]+bv[0])));
}

/* ------- softmax over V (in d_out) fused with gate scale + ext zero ------ */
__global__ void softmax_v(float* __restrict__ out){
  int rid = blockIdx.x;                 /* t*B + b */
  float* row = out + (long)rid*VE;
  int tid = threadIdx.x;                /* 512 */
  __shared__ float rm[512], rs[512];
  float m = row[tid], s = 1.f;
  for (int j=tid+512; j<VOC; j+=512){
    float x = row[j];
    if (x > m){ s = s*__expf(m-x) + 1.f; m = x; }
    else        s += __expf(x-m);
  }
  rm[tid]=m; rs[tid]=s; __syncthreads();
  for (int off=256; off>0; off>>=1){
    if (tid<off){
      float m2=rm[tid+off], s2=rs[tid+off];
      float M=fmaxf(rm[tid],m2);
      rs[tid]=rs[tid]*__expf(rm[tid]-M)+s2*__expf(m2-M);
      rm[tid]=M;
    }
    __syncthreads();
  }
  float M = rm[0];
  float gscale = g_gate[rid]/rs[0];
  for (int j=tid; j<VOC; j+=512) row[j] = __expf(row[j]-M)*gscale;
  for (int j=VOC+tid; j<VE; j+=512) row[j] = 0.f;
}

/* ---------------- scatter: pred[t,b,xids[s,b]] += (1-g)*dists ------------ */
__global__ void scatter_k(float* __restrict__ out, const int* __restrict__ xids){
  long i = (long)blockIdx.x*blockDim.x + threadIdx.x;
  if (i >= (long)TB*SEQ) return;
  int tb = (int)(i / SEQ);              /* t*B + b */
  int s  = (int)(i % SEQ);
  int b = tb % BATCH, t = tb / BATCH;
  float wv = g_w[((long)b*T_LEN + t)*SEQ + s];
  float gg = g_gate[tb];
  int col = xids[(long)s*BATCH + b];
  atomicAdd(out + (long)tb*VE + col, (1.f-gg)*wv);
}

/* ------------------------------- host ----------------------------------- */
static inline void launch_gemm(const GP& p, int batches){
  dim3 grid((p.M+BM-1)/BM, (p.N+BN-1)/BN, batches);
  gemm_tf32<<<grid, 256, GSMEM>>>(p);
}

extern "C" void kernel_launch(void* const* d_in, const int* in_sizes, int n_in,
                              void* d_out, int out_size){
  const float* h    = (const float*)d_in[0];
  const float* yemb = (const float*)d_in[1];
  const float* mem  = (const float*)d_in[2];
  const unsigned char* mask = (const unsigned char*)d_in[3];
  const int* xids   = (const int*)d_in[4];
  int wb = 5;
  if (n_in >= 18 && in_sizes[5] == 1) wb = 6;   /* max_ext_len scalar present */
  const float* Wq = (const float*)d_in[wb+0];
  const float* bq = (const float*)d_in[wb+1];
  const float* Wk = (const float*)d_in[wb+2];
  const float* bk = (const float*)d_in[wb+3];
  const float* Wv = (const float*)d_in[wb+4];
  const float* bva= (const float*)d_in[wb+5];
  const float* Wo = (const float*)d_in[wb+6];
  const float* bo = (const float*)d_in[wb+7];
  const float* Wp = (const float*)d_in[wb+8];
  const float* bp = (const float*)d_in[wb+9];
  const float* vv = (const float*)d_in[wb+10];
  const float* bv = (const float*)d_in[wb+11];

  float* out   = (float*)d_out;
  float* dists = out + (long)TB*VE;

  cudaFuncSetAttribute(gemm_tf32, cudaFuncAttributeMaxDynamicSharedMemorySize, GSMEM);

  void *qB, *kB, *valT, *wbuf, *attsB, *catp;
  cudaGetSymbolAddress(&qB,   g_qB);
  cudaGetSymbolAddress(&kB,   g_kB);
  cudaGetSymbolAddress(&valT, g_valT);
  cudaGetSymbolAddress(&wbuf, g_w);
  cudaGetSymbolAddress(&attsB,g_atts);
  cudaGetSymbolAddress(&catp, g_cat);

  float scale = 1.0f/sqrtf((float)HID);

  /* cat[:,0:1024] = [h, y_emb] */
  cat_copy<<<(TB*(HID/4)+255)/256, 256>>>(h, yemb);

  GP p;
  /* q = (h@Wq^T + bq)*scale  ->  (B,T,H) */
  p = GP{h, Wq, (float*)qB, HID, HID, HID, 0,0,0, TB, HID, HID,
         bq, scale, 1, BATCH, T_LEN, 0, 0};
  launch_gemm(p, 1);
  /* k = memory@Wk^T + bk  ->  (B,S,H) */
  p = GP{mem, Wk, (float*)kB, HID, HID, HID, 0,0,0, SEQ*BATCH, HID, HID,
         bk, 1.f, 1, BATCH, SEQ, 0, 0};
  launch_gemm(p, 1);
  /* val = memory@Wv^T + bv_attn  ->  (B,H,S) transposed */
  p = GP{mem, Wv, (float*)valT, HID, HID, 0, 0,0,0, SEQ*BATCH, HID, HID,
         bva, 1.f, 2, BATCH, HID, SEQ, 0};
  launch_gemm(p, 1);
  /* scores[b]: (T,S) = q_b @ k_b^T */
  p = GP{(const float*)qB, (const float*)kB, (float*)wbuf, HID, HID, SEQ,
         (long)T_LEN*HID, (long)SEQ*HID, (long)T_LEN*SEQ,
         T_LEN, SEQ, HID, nullptr, 1.f, 0, 0,0,0, 0};
  launch_gemm(p, BATCH);
  softmax_s<<<BATCH*T_LEN, 128>>>(dists, mask);
  /* atts[b]: (T,H) = w_b @ valT_b^T */
  p = GP{(const float*)wbuf, (const float*)valT, (float*)attsB, SEQ, SEQ, HID,
         (long)T_LEN*SEQ, (long)HID*SEQ, (long)T_LEN*HID,
         T_LEN, HID, SEQ, nullptr, 1.f, 0, 0,0,0, 0};
  launch_gemm(p, BATCH);
  /* cat[:,1024:1536] = atts@Wo^T + bo  (rows b*T+t -> t*B+b) */
  p = GP{(const float*)attsB, Wo, (float*)catp, HID, HID, H3, 0,0,0,
         TB, HID, HID, bo, 1.f, 1, T_LEN, BATCH, 0, 1024};
  launch_gemm(p, 1);
  gate_k<<<TB, 256>>>(vv, bv);
  /* logits = cat@Wp^T + bp  -> d_out rows, ldc = V+EXT */
  p = GP{(const float*)catp, Wp, out, H3, H3, VE, 0,0,0,
         TB, VOC, H3, bp, 1.f, 0, 0,0,0, 0};
  launch_gemm(p, 1);
  softmax_v<<<TB, 512>>>(out);
  scatter_k<<<(TB*SEQ + 255)/256, 256>>>(out, xids);

  (void)out_size; (void)n_in;
}